// round 4
// baseline (speedup 1.0000x reference)
#include <cuda_runtime.h>
#include <cstdint>

#define Bq 1024
#define Lq 100
#define NBLK 128
#define NTHR 512

typedef unsigned long long u64;

// ---------------- static scratch ----------------
__device__ float g_Wp0[1024 * 768];
__device__ float g_Wp1[1024 * 512];
__device__ float g_b0p[1024], g_b1p[1024];
__device__ float g_WaT[256 * 256];
__device__ float g_Wstack[512 * 256];     // rows 0..255 Wout, 256..511 Wco=Wcrit@Wout
__device__ float g_h0a[Bq * 256], g_h0b[Bq * 256];
__device__ float g_h1a[Bq * 256], g_h1b[Bq * 256];
__device__ float g_c0[Bq * 256], g_c1[Bq * 256];
__device__ float g_ctx[Bq * 256], g_ctx_att[Bq * 256];
__device__ float g_q[Bq * 256];
__device__ float g_logit[Bq * 256], g_Q[Bq * 256];
__device__ unsigned g_count;

// ---------------- f32x2 helpers ----------------
__device__ __forceinline__ float2 up2(u64 v) {
    float2 r; asm("mov.b64 {%0, %1}, %2;" : "=f"(r.x), "=f"(r.y) : "l"(v)); return r;
}
__device__ __forceinline__ void fma2(u64& d, u64 a, u64 b) {
    asm("fma.rn.f32x2 %0, %1, %2, %0;" : "+l"(d) : "l"(a), "l"(b));
}
__device__ __forceinline__ float sigm(float x) { return 1.f / (1.f + __expf(-x)); }

// ---------------- grid barrier ----------------
__device__ __forceinline__ void gsync(unsigned target) {
    __syncthreads();
    if (threadIdx.x == 0) {
        unsigned o;
        asm volatile("atom.add.release.gpu.u32 %0, [%1], 1;"
                     : "=r"(o) : "l"(&g_count) : "memory");
        unsigned cur;
        do {
            asm volatile("ld.acquire.gpu.u32 %0, [%1];"
                         : "=r"(cur) : "l"(&g_count) : "memory");
        } while ((int)(cur - target) < 0);
    }
    __syncthreads();
}

// ---------------- shared pool ----------------
struct SPool {
    union {
        struct { float Asd[2][16][264]; float Ws[2][16][68]; } gl;  // LSTM 128x64
        struct { float Asd[2][16][136]; float Ws[2][16][68]; } gs;  // small 64x64
        struct { float sc[8][104]; float part[8][256]; } att;
    };
};

// segmented A load (each segment 256 cols wide, row-major stride 256)
__device__ __forceinline__ float4 ldA(const float* A0, const float* A1, const float* A2,
                                      const int* gidx, bool gather, int bm, int r, int k) {
    int seg = k >> 8, kc = k & 255;
    const float* Ab = (seg == 0) ? A0 : (seg == 1 ? A1 : A2);
    const float* p = (gather && seg == 0) ? (Ab + (size_t)gidx[r] * 256 + kc)
                                          : (Ab + (size_t)(bm + r) * 256 + kc);
    return *(const float4*)p;
}

// ---------------- LSTM GEMM 128x64, duplicated-A smem, double-buffered -------
__device__ void lstm_gemm(SPool* sp, const int* gidx, int bm, int bn,
                          const float* A0, const float* A1, const float* A2, int Kt,
                          bool gather, const float* __restrict__ W,
                          const float* __restrict__ bias,
                          float* __restrict__ cst, float* __restrict__ hout) {
    const int tid = threadIdx.x;
    const int tx = tid & 15, ty = tid >> 4;        // 16 colgroups x 32 rowgroups
    const int r = tid >> 2, kq = (tid & 3) * 4;    // A loader: 128 rows x 4 kq
    const int rW = (tid & 255) >> 2, kqw = (tid & 3) * 4;  // W loader (tid<256)
    u64 acc[4][2];
#pragma unroll
    for (int i = 0; i < 4; i++) { acc[i][0] = 0ull; acc[i][1] = 0ull; }

    float4 pa = ldA(A0, A1, A2, gidx, gather, bm, r, kq);
    float4 pw;
    if (tid < 256) pw = *(const float4*)(W + (size_t)(bn + rW) * Kt + kqw);

    // store chunk 0 -> buf 0
    {
        float2* d0 = (float2*)&sp->gl.Asd[0][kq][2 * r];
        const int st = 264 / 2;  // float2 stride per kk row
        d0[0 * st] = make_float2(pa.x, pa.x);
        d0[1 * st] = make_float2(pa.y, pa.y);
        d0[2 * st] = make_float2(pa.z, pa.z);
        d0[3 * st] = make_float2(pa.w, pa.w);
        if (tid < 256) {
            sp->gl.Ws[0][kqw + 0][rW] = pw.x; sp->gl.Ws[0][kqw + 1][rW] = pw.y;
            sp->gl.Ws[0][kqw + 2][rW] = pw.z; sp->gl.Ws[0][kqw + 3][rW] = pw.w;
        }
    }
    const int nc = Kt >> 4;
    for (int c = 0; c < nc; c++) {
        const int buf = c & 1;
        __syncthreads();
        const bool more = (c + 1) < nc;
        if (more) {
            int kn = (c + 1) << 4;
            pa = ldA(A0, A1, A2, gidx, gather, bm, r, kn + kq);
            if (tid < 256) pw = *(const float4*)(W + (size_t)(bn + rW) * Kt + kn + kqw);
        }
#pragma unroll
        for (int kk = 0; kk < 16; kk++) {
            const float* asp = &sp->gl.Asd[buf][kk][ty * 8];
            ulonglong2 a01 = *(const ulonglong2*)asp;
            ulonglong2 a23 = *(const ulonglong2*)(asp + 4);
            ulonglong2 wp = *(const ulonglong2*)&sp->gl.Ws[buf][kk][tx * 4];
            fma2(acc[0][0], a01.x, wp.x); fma2(acc[0][1], a01.x, wp.y);
            fma2(acc[1][0], a01.y, wp.x); fma2(acc[1][1], a01.y, wp.y);
            fma2(acc[2][0], a23.x, wp.x); fma2(acc[2][1], a23.x, wp.y);
            fma2(acc[3][0], a23.y, wp.x); fma2(acc[3][1], a23.y, wp.y);
        }
        if (more) {
            const int nb = buf ^ 1;
            float2* d0 = (float2*)&sp->gl.Asd[nb][kq][2 * r];
            const int st = 264 / 2;
            d0[0 * st] = make_float2(pa.x, pa.x);
            d0[1 * st] = make_float2(pa.y, pa.y);
            d0[2 * st] = make_float2(pa.z, pa.z);
            d0[3 * st] = make_float2(pa.w, pa.w);
            if (tid < 256) {
                sp->gl.Ws[nb][kqw + 0][rW] = pw.x; sp->gl.Ws[nb][kqw + 1][rW] = pw.y;
                sp->gl.Ws[nb][kqw + 2][rW] = pw.z; sp->gl.Ws[nb][kqw + 3][rW] = pw.w;
            }
        }
    }
    // epilogue: cols tx*4+{0..3} = gates (i,f,g,o) of hidden h
    const int h = (bn >> 2) + tx;
    const float b0 = bias[bn + tx * 4 + 0], b1 = bias[bn + tx * 4 + 1];
    const float b2 = bias[bn + tx * 4 + 2], b3 = bias[bn + tx * 4 + 3];
#pragma unroll
    for (int rr = 0; rr < 4; rr++) {
        float2 gif = up2(acc[rr][0]);
        float2 ggo = up2(acc[rr][1]);
        float I = sigm(gif.x + b0), F = sigm(gif.y + b1);
        float G = tanhf(ggo.x + b2), Og = sigm(ggo.y + b3);
        int idx = (bm + ty * 4 + rr) * 256 + h;
        float cn = F * cst[idx] + I * G;
        cst[idx] = cn;
        hout[idx] = Og * tanhf(cn);
    }
}

// ---------------- small GEMM 64x64, duplicated-A, double-buffered ------------
// mode 0: store (+bias), 1: tanh store, 2: stacked split (C0 cols<256, C1 +bias)
__device__ void gemm_small(SPool* sp, int bm, int bn,
                           const float* A0, const float* A1, int Kt,
                           const float* __restrict__ W, const float* __restrict__ bias,
                           int mode, float* __restrict__ C0, float* __restrict__ C1) {
    const int tid = threadIdx.x;
    const int tx = tid & 15, ty = tid >> 4;   // 16 colgroups x 32 rowgroups
    u64 acc[2][2];
    acc[0][0] = acc[0][1] = acc[1][0] = acc[1][1] = 0ull;

    const int rA = tid >> 2, kqa = (tid & 3) * 4;        // tid<256
    const int t2 = tid - 256;
    const int rW = t2 >> 2, kqw = (t2 & 3) * 4;          // tid>=256
    float4 pa, pw;
    if (tid < 256) pa = ldA(A0, A1, nullptr, nullptr, false, bm, rA, kqa);
    else           pw = *(const float4*)(W + (size_t)(bn + rW) * Kt + kqw);

    {
        if (tid < 256) {
            float2* d0 = (float2*)&sp->gs.Asd[0][kqa][2 * rA];
            const int st = 136 / 2;
            d0[0 * st] = make_float2(pa.x, pa.x);
            d0[1 * st] = make_float2(pa.y, pa.y);
            d0[2 * st] = make_float2(pa.z, pa.z);
            d0[3 * st] = make_float2(pa.w, pa.w);
        } else {
            sp->gs.Ws[0][kqw + 0][rW] = pw.x; sp->gs.Ws[0][kqw + 1][rW] = pw.y;
            sp->gs.Ws[0][kqw + 2][rW] = pw.z; sp->gs.Ws[0][kqw + 3][rW] = pw.w;
        }
    }
    const int nc = Kt >> 4;
    for (int c = 0; c < nc; c++) {
        const int buf = c & 1;
        __syncthreads();
        const bool more = (c + 1) < nc;
        if (more) {
            int kn = (c + 1) << 4;
            if (tid < 256) pa = ldA(A0, A1, nullptr, nullptr, false, bm, rA, kn + kqa);
            else           pw = *(const float4*)(W + (size_t)(bn + rW) * Kt + kn + kqw);
        }
#pragma unroll
        for (int kk = 0; kk < 16; kk++) {
            ulonglong2 a = *(const ulonglong2*)&sp->gs.Asd[buf][kk][ty * 4];
            ulonglong2 wp = *(const ulonglong2*)&sp->gs.Ws[buf][kk][tx * 4];
            fma2(acc[0][0], a.x, wp.x); fma2(acc[0][1], a.x, wp.y);
            fma2(acc[1][0], a.y, wp.x); fma2(acc[1][1], a.y, wp.y);
        }
        if (more) {
            const int nb = buf ^ 1;
            if (tid < 256) {
                float2* d0 = (float2*)&sp->gs.Asd[nb][kqa][2 * rA];
                const int st = 136 / 2;
                d0[0 * st] = make_float2(pa.x, pa.x);
                d0[1 * st] = make_float2(pa.y, pa.y);
                d0[2 * st] = make_float2(pa.z, pa.z);
                d0[3 * st] = make_float2(pa.w, pa.w);
            } else {
                sp->gs.Ws[nb][kqw + 0][rW] = pw.x; sp->gs.Ws[nb][kqw + 1][rW] = pw.y;
                sp->gs.Ws[nb][kqw + 2][rW] = pw.z; sp->gs.Ws[nb][kqw + 3][rW] = pw.w;
            }
        }
    }
#pragma unroll
    for (int rr = 0; rr < 2; rr++) {
        int row = bm + ty * 2 + rr;
#pragma unroll
        for (int p = 0; p < 2; p++) {
            float2 v = up2(acc[rr][p]);
#pragma unroll
            for (int e = 0; e < 2; e++) {
                int col = bn + tx * 4 + 2 * p + e;
                float val = e ? v.y : v.x;
                if (mode == 2) {
                    if (col < 256) C0[(size_t)row * 256 + col] = val;
                    else C1[(size_t)row * 256 + (col - 256)] = val + bias[col - 256];
                } else {
                    if (bias) val += bias[col];
                    if (mode == 1) val = tanhf(val);
                    C0[(size_t)row * 256 + col] = val;
                }
            }
        }
    }
}

// ---------------- attention: 8 rows concurrent, 2 warps/row ------------------
__device__ void attention8(SPool* sp, int bid, const float* __restrict__ eo) {
    const int tid = threadIdx.x, w = tid >> 5, lane = tid & 31;
    const int r8 = w >> 1, half = w & 1, b = bid * 8 + r8;
    float4 q0 = *(const float4*)(g_q + b * 256 + lane * 4);
    float4 q1 = *(const float4*)(g_q + b * 256 + 128 + lane * 4);
    const float* eb = eo + (size_t)b * Lq * 256;
    const int l0 = half * 50;
#pragma unroll 2
    for (int l = l0; l < l0 + 50; l++) {
        const float* p = eb + (size_t)l * 256;
        float4 v0 = *(const float4*)(p + lane * 4);
        float4 v1 = *(const float4*)(p + 128 + lane * 4);
        float s = v0.x * q0.x + v0.y * q0.y + v0.z * q0.z + v0.w * q0.w
                + v1.x * q1.x + v1.y * q1.y + v1.z * q1.z + v1.w * q1.w;
#pragma unroll
        for (int o = 16; o; o >>= 1) s += __shfl_xor_sync(0xFFFFFFFFu, s, o);
        if (!lane) sp->att.sc[r8][l] = s;
    }
    __syncthreads();
    float x0 = sp->att.sc[r8][lane];
    float x1 = sp->att.sc[r8][lane + 32];
    float x2 = sp->att.sc[r8][lane + 64];
    bool v3 = (lane + 96) < Lq;
    float x3 = v3 ? sp->att.sc[r8][lane + 96] : -1e30f;
    float m = fmaxf(fmaxf(x0, x1), fmaxf(x2, x3));
#pragma unroll
    for (int o = 16; o; o >>= 1) m = fmaxf(m, __shfl_xor_sync(0xFFFFFFFFu, m, o));
    float es = __expf(x0 - m) + __expf(x1 - m) + __expf(x2 - m) + (v3 ? __expf(x3 - m) : 0.f);
#pragma unroll
    for (int o = 16; o; o >>= 1) es += __shfl_xor_sync(0xFFFFFFFFu, es, o);
    float inv = 1.f / es;
    float4 a0 = make_float4(0, 0, 0, 0), a1 = make_float4(0, 0, 0, 0);
#pragma unroll 2
    for (int l = l0; l < l0 + 50; l++) {
        float wgt = __expf(sp->att.sc[r8][l] - m) * inv;
        const float* p = eb + (size_t)l * 256;
        float4 v0 = *(const float4*)(p + lane * 4);
        float4 v1 = *(const float4*)(p + 128 + lane * 4);
        a0.x += wgt * v0.x; a0.y += wgt * v0.y; a0.z += wgt * v0.z; a0.w += wgt * v0.w;
        a1.x += wgt * v1.x; a1.y += wgt * v1.y; a1.z += wgt * v1.z; a1.w += wgt * v1.w;
    }
    if (half) {
        *(float4*)&sp->att.part[r8][lane * 4] = a0;
        *(float4*)&sp->att.part[r8][128 + lane * 4] = a1;
    }
    __syncthreads();
    if (!half) {
        float4 p0 = *(const float4*)&sp->att.part[r8][lane * 4];
        float4 p1 = *(const float4*)&sp->att.part[r8][128 + lane * 4];
        a0.x += p0.x; a0.y += p0.y; a0.z += p0.z; a0.w += p0.w;
        a1.x += p1.x; a1.y += p1.y; a1.z += p1.z; a1.w += p1.w;
        *(float4*)(g_ctx_att + b * 256 + lane * 4) = a0;
        *(float4*)(g_ctx_att + b * 256 + 128 + lane * 4) = a1;
    }
}

// ---------------- finalize: warp-per-row, no block barriers ------------------
__device__ void finalize8(int bid, int t, const int* __restrict__ actions,
                          float* __restrict__ out) {
    const int w = threadIdx.x >> 5, lane = threadIdx.x & 31;
    if (w >= 8) return;
    const int b = bid * 8 + w;
    const float* lr = g_logit + b * 256;
    float4 l0 = *(const float4*)(lr + lane * 4);
    float4 l1 = *(const float4*)(lr + 128 + lane * 4);
    float m = fmaxf(fmaxf(fmaxf(l0.x, l0.y), fmaxf(l0.z, l0.w)),
                    fmaxf(fmaxf(l1.x, l1.y), fmaxf(l1.z, l1.w)));
#pragma unroll
    for (int o = 16; o; o >>= 1) m = fmaxf(m, __shfl_xor_sync(0xFFFFFFFFu, m, o));
    float4 e0 = make_float4(__expf(l0.x - m), __expf(l0.y - m), __expf(l0.z - m), __expf(l0.w - m));
    float4 e1 = make_float4(__expf(l1.x - m), __expf(l1.y - m), __expf(l1.z - m), __expf(l1.w - m));
    float s = e0.x + e0.y + e0.z + e0.w + e1.x + e1.y + e1.z + e1.w;
#pragma unroll
    for (int o = 16; o; o >>= 1) s += __shfl_xor_sync(0xFFFFFFFFu, s, o);
    float inv = 1.f / s;
    e0.x *= inv; e0.y *= inv; e0.z *= inv; e0.w *= inv;
    e1.x *= inv; e1.y *= inv; e1.z *= inv; e1.w *= inv;
    float* outl = out + (size_t)Bq * Lq + ((size_t)b * Lq + t) * 256;
    *(float4*)(outl + lane * 4) = e0;
    *(float4*)(outl + 128 + lane * 4) = e1;
    const float* Qr = g_Q + b * 256;
    float4 Q0 = *(const float4*)(Qr + lane * 4);
    float4 Q1 = *(const float4*)(Qr + 128 + lane * 4);
    float v = e0.x * Q0.x + e0.y * Q0.y + e0.z * Q0.z + e0.w * Q0.w
            + e1.x * Q1.x + e1.y * Q1.y + e1.z * Q1.z + e1.w * Q1.w;
#pragma unroll
    for (int o = 16; o; o >>= 1) v += __shfl_xor_sync(0xFFFFFFFFu, v, o);
    if (!lane) {
        out[(size_t)Bq * Lq + (size_t)Bq * Lq * 256 + b * Lq + t] = v;
        out[b * Lq + t] = (float)actions[b * Lq + t];
    }
}

// ---------------- persistent mega-kernel ----------------
__global__ void __launch_bounds__(NTHR, 1)
mega(const float* __restrict__ enc_out, const float* __restrict__ enc_h,
     const float* __restrict__ enc_c, const float* __restrict__ emb,
     const float* __restrict__ Wih0, const float* __restrict__ Whh0,
     const float* __restrict__ bih0, const float* __restrict__ bhh0,
     const float* __restrict__ Wih1, const float* __restrict__ Whh1,
     const float* __restrict__ bih1, const float* __restrict__ bhh1,
     const float* __restrict__ Wa, const float* __restrict__ Wconcat,
     const float* __restrict__ Wout, const float* __restrict__ Wcrit,
     const float* __restrict__ bcrit, const int* __restrict__ actions,
     float* __restrict__ out) {
    extern __shared__ float dynsm[];
    SPool* sp = (SPool*)dynsm;
    __shared__ int gidx[128];
    const int bid = blockIdx.x, tid = threadIdx.x;
    unsigned bt = 0;

    // ---- phase 0: weight permute, WaT, Wstack(Wout|Wcrit@Wout), state init --
    for (int idx = bid * NTHR + tid; idx < 1024 * 768; idx += NBLK * NTHR) {
        int n = idx / 768, k = idx - n * 768;
        int h = n >> 2, g = n & 3, orow = g * 256 + h;
        g_Wp0[idx] = (k < 512) ? Wih0[orow * 512 + k] : Whh0[orow * 256 + (k - 512)];
    }
    for (int idx = bid * NTHR + tid; idx < 1024 * 512; idx += NBLK * NTHR) {
        int n = idx / 512, k = idx - n * 512;
        int h = n >> 2, g = n & 3, orow = g * 256 + h;
        g_Wp1[idx] = (k < 256) ? Wih1[orow * 256 + k] : Whh1[orow * 256 + (k - 256)];
    }
    for (int idx = bid * NTHR + tid; idx < 65536; idx += NBLK * NTHR) {
        int k = idx >> 8, h = idx & 255;
        g_WaT[idx] = Wa[h * 256 + k];
        g_Wstack[idx] = Wout[idx];
    }
    {   // Wco = Wcrit @ Wout : one output per thread
        int g = bid * NTHR + tid;           // 65536 threads exactly
        int i = g >> 8, j = g & 255;
        float acc = 0.f;
        const float* wc = Wcrit + i * 256;
#pragma unroll 4
        for (int k = 0; k < 256; k++) acc += wc[k] * Wout[k * 256 + j];
        g_Wstack[65536 + i * 256 + j] = acc;
    }
    for (int idx = bid * NTHR + tid; idx < 1024; idx += NBLK * NTHR) {
        int h = idx >> 2, g = idx & 3, orow = g * 256 + h;
        g_b0p[idx] = bih0[orow] + bhh0[orow];
        g_b1p[idx] = bih1[orow] + bhh1[orow];
    }
    for (int idx = bid * NTHR + tid; idx < Bq * 256; idx += NBLK * NTHR) {
        g_h0a[idx] = enc_h[idx]; g_h1a[idx] = enc_h[Bq * 256 + idx];
        g_c0[idx] = enc_c[idx];  g_c1[idx] = enc_c[Bq * 256 + idx];
        int b = idx >> 8, hh = idx & 255;
        const float* p = enc_out + (size_t)b * Lq * 256 + hh;
        float s = 0.f;
        for (int l = 0; l < Lq; l++) s += p[(size_t)l * 256];
        g_ctx[idx] = s * (1.0f / Lq);
    }
    bt += NBLK; gsync(bt);

    float *h0c = g_h0a, *h0n = g_h0b, *h1c = g_h1a, *h1n = g_h1b;
    const int bmL = (bid >> 4) * 128, bnL = (bid & 15) * 64;

    for (int t = 0; t < Lq; t++) {
        // P1: LSTM0
        if (tid < 128)
            gidx[tid] = (t == 0) ? 0 : actions[(bmL + tid) * Lq + (t - 1)];
        __syncthreads();
        lstm_gemm(sp, gidx, bmL, bnL, emb, g_ctx, h0c, 768, true, g_Wp0, g_b0p, g_c0, h0n);
        bt += NBLK; gsync(bt);
        // P2: LSTM1
        lstm_gemm(sp, gidx, bmL, bnL, h0n, h1c, nullptr, 512, false, g_Wp1, g_b1p, g_c1, h1n);
        bt += NBLK; gsync(bt);
        // P3: q = h1 @ Wa (blocks 0..63); others prefetch their attention rows
        if (bid < 64) {
            gemm_small(sp, (bid >> 2) * 64, (bid & 3) * 64, h1n, nullptr, 256,
                       g_WaT, nullptr, 0, g_q, nullptr);
        } else {
            const char* base = (const char*)(enc_out + (size_t)bid * 8 * Lq * 256);
            const int tot = 8 * Lq * 256 * 4;
            for (int off = tid * 128; off < tot; off += NTHR * 128)
                asm volatile("prefetch.global.L2 [%0];" :: "l"(base + off));
            __syncthreads();
        }
        bt += NBLK; gsync(bt);
        // P4: attention
        attention8(sp, bid, enc_out);
        bt += NBLK; gsync(bt);
        // P5: ctx = tanh([h1|ctx_att] @ Wconcat^T) (blocks 0..63)
        if (bid < 64)
            gemm_small(sp, (bid >> 2) * 64, (bid & 3) * 64, h1n, g_ctx_att, 512,
                       Wconcat, nullptr, 1, g_ctx, nullptr);
        bt += NBLK; gsync(bt);
        // P6: [logit | Q] = ctx @ [Wout;Wco]^T (stacked, 128 blocks)
        gemm_small(sp, (bid >> 3) * 64, (bid & 7) * 64, g_ctx, nullptr, 256,
                   g_Wstack, bcrit, 2, g_logit, g_Q);
        bt += NBLK; gsync(bt);
        // P7: finalize (warp-per-row, no barriers)
        finalize8(bid, t, actions, out);
        float* tmp = h0c; h0c = h0n; h0n = tmp;
        tmp = h1c; h1c = h1n; h1n = tmp;
    }
}

__global__ void reset_k() { g_count = 0; }

// ---------------- host ----------------
extern "C" void kernel_launch(void* const* d_in, const int* in_sizes, int n_in,
                              void* d_out, int out_size) {
    const float* enc_out = (const float*)d_in[0];
    const float* enc_h   = (const float*)d_in[1];
    const float* enc_c   = (const float*)d_in[2];
    const float* emb     = (const float*)d_in[3];
    const float* Wih0    = (const float*)d_in[4];
    const float* Whh0    = (const float*)d_in[5];
    const float* bih0    = (const float*)d_in[6];
    const float* bhh0    = (const float*)d_in[7];
    const float* Wih1    = (const float*)d_in[8];
    const float* Whh1    = (const float*)d_in[9];
    const float* bih1    = (const float*)d_in[10];
    const float* bhh1    = (const float*)d_in[11];
    const float* Wa      = (const float*)d_in[12];
    const float* Wconcat = (const float*)d_in[13];
    const float* Wout    = (const float*)d_in[14];
    const float* Wcrit   = (const float*)d_in[15];
    const float* bcrit   = (const float*)d_in[16];
    const int*   actions = (const int*)d_in[17];
    float* out = (float*)d_out;

    const int smem = (int)sizeof(SPool);
    cudaFuncSetAttribute(mega, cudaFuncAttributeMaxDynamicSharedMemorySize, smem);
    reset_k<<<1, 1>>>();
    mega<<<NBLK, NTHR, smem>>>(enc_out, enc_h, enc_c, emb,
                               Wih0, Whh0, bih0, bhh0,
                               Wih1, Whh1, bih1, bhh1,
                               Wa, Wconcat, Wout, Wcrit, bcrit, actions, out);
}

// round 5
// speedup vs baseline: 1.0751x; 1.0751x over previous
#include <cuda_runtime.h>
#include <cstdint>

#define Bq 1024
#define Lq 100
#define NBLK 128
#define NTHR 512

typedef unsigned long long u64;

// ---------------- static scratch ----------------
__device__ float g_Wp0[1024 * 768];
__device__ float g_Wp1[1024 * 512];
__device__ float g_b0p[1024], g_b1p[1024];
__device__ float g_WaT[256 * 256];
__device__ float g_Wstack[512 * 256];     // rows 0..255 Wout, 256..511 Wco=Wcrit@Wout
__device__ float g_h0a[Bq * 256], g_h0b[Bq * 256];
__device__ float g_h1a[Bq * 256], g_h1b[Bq * 256];
__device__ float g_c0[Bq * 256], g_c1[Bq * 256];
__device__ float g_ctx[Bq * 256], g_ctx_att[Bq * 256];
__device__ float g_q[Bq * 256];
__device__ float g_logit[Bq * 256], g_Q[Bq * 256];
__device__ unsigned g_count;

// ---------------- f32x2 helpers ----------------
__device__ __forceinline__ u64 pk2(float lo, float hi) {
    u64 r; asm("mov.b64 %0, {%1, %2};" : "=l"(r) : "f"(lo), "f"(hi)); return r;
}
__device__ __forceinline__ float2 up2(u64 v) {
    float2 r; asm("mov.b64 {%0, %1}, %2;" : "=f"(r.x), "=f"(r.y) : "l"(v)); return r;
}
__device__ __forceinline__ void fma2(u64& d, u64 a, u64 b) {
    asm("fma.rn.f32x2 %0, %1, %2, %0;" : "+l"(d) : "l"(a), "l"(b));
}
__device__ __forceinline__ float sigm(float x) { return 1.f / (1.f + __expf(-x)); }

// ---------------- grid barrier ----------------
__device__ __forceinline__ void gsync(unsigned target) {
    __syncthreads();
    if (threadIdx.x == 0) {
        unsigned o;
        asm volatile("atom.add.release.gpu.u32 %0, [%1], 1;"
                     : "=r"(o) : "l"(&g_count) : "memory");
        unsigned cur;
        do {
            asm volatile("ld.acquire.gpu.u32 %0, [%1];"
                         : "=r"(cur) : "l"(&g_count) : "memory");
        } while ((int)(cur - target) < 0);
    }
    __syncthreads();
}

// ---------------- shared pool ----------------
struct SPool {
    union {
        struct { float As[2][32][132]; float Ws[2][32][68]; } l;   // LSTM double-buffer
        struct { float As[16][34]; float Ws[16][68]; } s;          // small GEMM
        struct { float acc[8][256]; float m1[8]; float e1[8]; } att;
    };
};

// =============== LSTM GEMM 128x64, warp-specialized, K-chunk 32 ==============
// tid<256 compute (grid 32 rowgroups x 8 colgroups, TM=4, TN=8 gate-cols),
// tid>=256 load. W gate-interleaved so cols cg*8..+7 = gates of 2 hiddens.
__device__ void lstm_gemm(SPool* sp, const int* gidx, int bm, int bn,
                          const float* A0, const float* A1, const float* A2, int Kt,
                          bool gather, const float* __restrict__ W,
                          const float* __restrict__ bias,
                          float* __restrict__ cst, float* __restrict__ hout) {
    const int tid = threadIdx.x;
    const int nc = Kt >> 5;
    if (tid < 256) {
        const int rg = tid >> 3, cg = tid & 7;
        u64 acc[4][4];
#pragma unroll
        for (int r = 0; r < 4; r++)
#pragma unroll
            for (int j = 0; j < 4; j++) acc[r][j] = 0ull;

        for (int c = 0; c < nc; c++) {
            __syncthreads();
            const float (*As)[132] = sp->l.As[c & 1];
            const float (*Ws)[68] = sp->l.Ws[c & 1];
#pragma unroll
            for (int kk = 0; kk < 32; kk++) {
                float4 av = *(const float4*)&As[kk][rg * 4];
                u64 a0 = pk2(av.x, av.x), a1 = pk2(av.y, av.y);
                u64 a2 = pk2(av.z, av.z), a3 = pk2(av.w, av.w);
                ulonglong2 w01 = *(const ulonglong2*)&Ws[kk][cg * 8];
                ulonglong2 w23 = *(const ulonglong2*)&Ws[kk][cg * 8 + 4];
                fma2(acc[0][0], a0, w01.x); fma2(acc[0][1], a0, w01.y);
                fma2(acc[0][2], a0, w23.x); fma2(acc[0][3], a0, w23.y);
                fma2(acc[1][0], a1, w01.x); fma2(acc[1][1], a1, w01.y);
                fma2(acc[1][2], a1, w23.x); fma2(acc[1][3], a1, w23.y);
                fma2(acc[2][0], a2, w01.x); fma2(acc[2][1], a2, w01.y);
                fma2(acc[2][2], a2, w23.x); fma2(acc[2][3], a2, w23.y);
                fma2(acc[3][0], a3, w01.x); fma2(acc[3][1], a3, w01.y);
                fma2(acc[3][2], a3, w23.x); fma2(acc[3][3], a3, w23.y);
            }
        }
        // epilogue: LSTM cell for 4 rows x 2 hiddens
        const int nb = bn + cg * 8;
        const float bi0 = bias[nb + 0], bf0 = bias[nb + 1];
        const float bg0 = bias[nb + 2], bo0 = bias[nb + 3];
        const float bi1 = bias[nb + 4], bf1 = bias[nb + 5];
        const float bg1 = bias[nb + 6], bo1 = bias[nb + 7];
        const int h0 = (bn >> 2) + cg * 2;
#pragma unroll
        for (int r = 0; r < 4; r++) {
            const int row = bm + rg * 4 + r;
            {
                float2 if0 = up2(acc[r][0]);
                float2 go0 = up2(acc[r][1]);
                float I = sigm(if0.x + bi0), F = sigm(if0.y + bf0);
                float G = tanhf(go0.x + bg0), Og = sigm(go0.y + bo0);
                int idx = row * 256 + h0;
                float cn = F * cst[idx] + I * G;
                cst[idx] = cn; hout[idx] = Og * tanhf(cn);
            }
            {
                float2 if1 = up2(acc[r][2]);
                float2 go1 = up2(acc[r][3]);
                float I = sigm(if1.x + bi1), F = sigm(if1.y + bf1);
                float G = tanhf(go1.x + bg1), Og = sigm(go1.y + bo1);
                int idx = row * 256 + h0 + 1;
                float cn = F * cst[idx] + I * G;
                cst[idx] = cn; hout[idx] = Og * tanhf(cn);
            }
        }
    } else {
        // loader warps
        const int lt = tid - 256;
        // fill chunk 0 -> buf 0
        for (int c = -1; c < nc; c++) {
            if (c >= 0) __syncthreads();
            const int cn = c + 1;
            if (cn >= nc) continue;
            const int b = cn & 1;
            const int k0 = cn << 5;
#pragma unroll
            for (int i = 0; i < 4; i++) {
                int a = lt + 256 * i;
                int row = a & 127, kq = (a >> 7) * 4;
                int k = k0 + kq;
                int seg = k >> 8, kc = k & 255;
                const float* Ab = (seg == 0) ? A0 : (seg == 1 ? A1 : A2);
                const float* p = (gather && seg == 0)
                                 ? (Ab + (size_t)gidx[row] * 256 + kc)
                                 : (Ab + (size_t)(bm + row) * 256 + kc);
                float4 v = *(const float4*)p;
                sp->l.As[b][kq + 0][row] = v.x; sp->l.As[b][kq + 1][row] = v.y;
                sp->l.As[b][kq + 2][row] = v.z; sp->l.As[b][kq + 3][row] = v.w;
            }
#pragma unroll
            for (int i = 0; i < 2; i++) {
                int w = lt + 256 * i;
                int col = w & 63, kq = (w >> 6) * 4;
                float4 v = *(const float4*)(W + (size_t)(bn + col) * Kt + k0 + kq);
                sp->l.Ws[b][kq + 0][col] = v.x; sp->l.Ws[b][kq + 1][col] = v.y;
                sp->l.Ws[b][kq + 2][col] = v.z; sp->l.Ws[b][kq + 3][col] = v.w;
            }
        }
    }
}

// =============== small GEMM 32x64, 512 threads, K-chunk 16 ===================
__device__ void gemm_small(SPool* sp, int bm, int bn,
                           const float* A0, const float* A1, int Kt,
                           const float* __restrict__ W, const float* __restrict__ bias,
                           int dotanh, float* __restrict__ C, int colbase) {
    const int tid = threadIdx.x;
    const int rg = tid >> 5, cg = tid & 31;      // 16 rowgroups x 32 colgroups
    u64 acc0 = 0ull, acc1 = 0ull;

    const bool isA = tid < 128, isW = (tid >= 128 && tid < 384);
    const int rowA = tid & 31, kqA = (tid >> 5) * 4;
    const int wt = tid - 128;
    const int colW = wt & 63, kqW = (wt >> 6) * 4;

    float4 pa, pw;
    if (isA) {
        int seg = 0, kc = kqA;
        const float* Ab = seg ? A1 : A0;
        pa = *(const float4*)(Ab + (size_t)(bm + rowA) * 256 + kc);
    }
    if (isW) pw = *(const float4*)(W + (size_t)(bn + colW) * Kt + kqW);

    const int nc = Kt >> 4;
    for (int c = 0; c < nc; c++) {
        if (isA) {
            sp->s.As[kqA + 0][rowA] = pa.x; sp->s.As[kqA + 1][rowA] = pa.y;
            sp->s.As[kqA + 2][rowA] = pa.z; sp->s.As[kqA + 3][rowA] = pa.w;
        }
        if (isW) {
            sp->s.Ws[kqW + 0][colW] = pw.x; sp->s.Ws[kqW + 1][colW] = pw.y;
            sp->s.Ws[kqW + 2][colW] = pw.z; sp->s.Ws[kqW + 3][colW] = pw.w;
        }
        __syncthreads();
        const int kn = (c + 1) << 4;
        if (kn < Kt) {
            if (isA) {
                int k = kn + kqA, seg = k >> 8, kc = k & 255;
                const float* Ab = seg ? A1 : A0;
                pa = *(const float4*)(Ab + (size_t)(bm + rowA) * 256 + kc);
            }
            if (isW) pw = *(const float4*)(W + (size_t)(bn + colW) * Kt + kn + kqW);
        }
#pragma unroll
        for (int kk = 0; kk < 16; kk++) {
            float2 a = *(const float2*)&sp->s.As[kk][rg * 2];
            u64 wv = *(const u64*)&sp->s.Ws[kk][cg * 2];
            fma2(acc0, pk2(a.x, a.x), wv);
            fma2(acc1, pk2(a.y, a.y), wv);
        }
        __syncthreads();
    }
#pragma unroll
    for (int j = 0; j < 2; j++) {
        float2 v = up2(j ? acc1 : acc0);
        int row = bm + rg * 2 + j;
        int c0 = colbase + cg * 2;
        float v0 = v.x, v1 = v.y;
        if (bias) { v0 += bias[c0]; v1 += bias[c0 + 1]; }
        if (dotanh) { v0 = tanhf(v0); v1 = tanhf(v1); }
        C[(size_t)row * 256 + c0] = v0;
        C[(size_t)row * 256 + c0 + 1] = v1;
    }
}

// =============== single-pass online-softmax attention, 8 rows/block ==========
__device__ void attention8(SPool* sp, int bid, const float* __restrict__ eo) {
    const int tid = threadIdx.x, w = tid >> 5, lane = tid & 31;
    const int r8 = w >> 1, half = w & 1, b = bid * 8 + r8;
    const float* qb = g_q + b * 256;
    float4 q0 = *(const float4*)(qb + lane * 4);
    float4 q1 = *(const float4*)(qb + 128 + lane * 4);
    const float* eb = eo + (size_t)b * Lq * 256;
    float m = -1e30f, esum = 0.f;
    float4 a0 = make_float4(0, 0, 0, 0), a1 = make_float4(0, 0, 0, 0);
    const int l0 = half * 50;
#pragma unroll 2
    for (int l = l0; l < l0 + 50; l++) {
        const float* p = eb + (size_t)l * 256;
        float4 v0 = *(const float4*)(p + lane * 4);
        float4 v1 = *(const float4*)(p + 128 + lane * 4);
        float s = v0.x * q0.x + v0.y * q0.y + v0.z * q0.z + v0.w * q0.w
                + v1.x * q1.x + v1.y * q1.y + v1.z * q1.z + v1.w * q1.w;
#pragma unroll
        for (int o = 16; o; o >>= 1) s += __shfl_xor_sync(0xFFFFFFFFu, s, o);
        if (s <= m) {
            float wgt = __expf(s - m);
            esum += wgt;
            a0.x += wgt * v0.x; a0.y += wgt * v0.y; a0.z += wgt * v0.z; a0.w += wgt * v0.w;
            a1.x += wgt * v1.x; a1.y += wgt * v1.y; a1.z += wgt * v1.z; a1.w += wgt * v1.w;
        } else {
            float r = __expf(m - s);
            esum = esum * r + 1.f;
            a0.x = a0.x * r + v0.x; a0.y = a0.y * r + v0.y;
            a0.z = a0.z * r + v0.z; a0.w = a0.w * r + v0.w;
            a1.x = a1.x * r + v1.x; a1.y = a1.y * r + v1.y;
            a1.z = a1.z * r + v1.z; a1.w = a1.w * r + v1.w;
            m = s;
        }
    }
    if (half) {
        sp->att.m1[r8] = m; sp->att.e1[r8] = esum;
        *(float4*)&sp->att.acc[r8][lane * 4] = a0;
        *(float4*)&sp->att.acc[r8][128 + lane * 4] = a1;
    }
    __syncthreads();
    if (!half) {
        float m1 = sp->att.m1[r8], e1 = sp->att.e1[r8];
        float M = fmaxf(m, m1);
        float r0 = __expf(m - M), r1 = __expf(m1 - M);
        float inv = 1.f / (esum * r0 + e1 * r1);
        float4 p0 = *(const float4*)&sp->att.acc[r8][lane * 4];
        float4 p1 = *(const float4*)&sp->att.acc[r8][128 + lane * 4];
        float4 o0, o1;
        o0.x = (a0.x * r0 + p0.x * r1) * inv; o0.y = (a0.y * r0 + p0.y * r1) * inv;
        o0.z = (a0.z * r0 + p0.z * r1) * inv; o0.w = (a0.w * r0 + p0.w * r1) * inv;
        o1.x = (a1.x * r0 + p1.x * r1) * inv; o1.y = (a1.y * r0 + p1.y * r1) * inv;
        o1.z = (a1.z * r0 + p1.z * r1) * inv; o1.w = (a1.w * r0 + p1.w * r1) * inv;
        *(float4*)(g_ctx_att + b * 256 + lane * 4) = o0;
        *(float4*)(g_ctx_att + b * 256 + 128 + lane * 4) = o1;
    }
    __syncthreads();
}

// =============== finalize: warp-per-row ======================================
__device__ void finalize8(int bid, int t, const int* __restrict__ actions,
                          float* __restrict__ out) {
    const int w = threadIdx.x >> 5, lane = threadIdx.x & 31;
    if (w >= 8) return;
    const int b = bid * 8 + w;
    const float* lr = g_logit + b * 256;
    float4 l0 = *(const float4*)(lr + lane * 4);
    float4 l1 = *(const float4*)(lr + 128 + lane * 4);
    float m = fmaxf(fmaxf(fmaxf(l0.x, l0.y), fmaxf(l0.z, l0.w)),
                    fmaxf(fmaxf(l1.x, l1.y), fmaxf(l1.z, l1.w)));
#pragma unroll
    for (int o = 16; o; o >>= 1) m = fmaxf(m, __shfl_xor_sync(0xFFFFFFFFu, m, o));
    float4 e0 = make_float4(__expf(l0.x - m), __expf(l0.y - m), __expf(l0.z - m), __expf(l0.w - m));
    float4 e1 = make_float4(__expf(l1.x - m), __expf(l1.y - m), __expf(l1.z - m), __expf(l1.w - m));
    float s = e0.x + e0.y + e0.z + e0.w + e1.x + e1.y + e1.z + e1.w;
#pragma unroll
    for (int o = 16; o; o >>= 1) s += __shfl_xor_sync(0xFFFFFFFFu, s, o);
    float inv = 1.f / s;
    e0.x *= inv; e0.y *= inv; e0.z *= inv; e0.w *= inv;
    e1.x *= inv; e1.y *= inv; e1.z *= inv; e1.w *= inv;
    float* outl = out + (size_t)Bq * Lq + ((size_t)b * Lq + t) * 256;
    *(float4*)(outl + lane * 4) = e0;
    *(float4*)(outl + 128 + lane * 4) = e1;
    const float* Qr = g_Q + b * 256;
    float4 Q0 = *(const float4*)(Qr + lane * 4);
    float4 Q1 = *(const float4*)(Qr + 128 + lane * 4);
    float v = e0.x * Q0.x + e0.y * Q0.y + e0.z * Q0.z + e0.w * Q0.w
            + e1.x * Q1.x + e1.y * Q1.y + e1.z * Q1.z + e1.w * Q1.w;
#pragma unroll
    for (int o = 16; o; o >>= 1) v += __shfl_xor_sync(0xFFFFFFFFu, v, o);
    if (!lane) {
        out[(size_t)Bq * Lq + (size_t)Bq * Lq * 256 + b * Lq + t] = v;
        out[b * Lq + t] = (float)actions[b * Lq + t];
    }
}

// =============== persistent mega-kernel ======================================
__global__ void __launch_bounds__(NTHR, 1)
mega(const float* __restrict__ enc_out, const float* __restrict__ enc_h,
     const float* __restrict__ enc_c, const float* __restrict__ emb,
     const float* __restrict__ Wih0, const float* __restrict__ Whh0,
     const float* __restrict__ bih0, const float* __restrict__ bhh0,
     const float* __restrict__ Wih1, const float* __restrict__ Whh1,
     const float* __restrict__ bih1, const float* __restrict__ bhh1,
     const float* __restrict__ Wa, const float* __restrict__ Wconcat,
     const float* __restrict__ Wout, const float* __restrict__ Wcrit,
     const float* __restrict__ bcrit, const int* __restrict__ actions,
     float* __restrict__ out) {
    extern __shared__ float dynsm[];
    SPool* sp = (SPool*)dynsm;
    __shared__ int gidx[128];
    const int bid = blockIdx.x, tid = threadIdx.x;
    unsigned bt = 0;

    // ---- init: permuted weights, WaT, Wstack, states, ctx0 ----
    for (int idx = bid * NTHR + tid; idx < 1024 * 768; idx += NBLK * NTHR) {
        int n = idx / 768, k = idx - n * 768;
        int h = n >> 2, g = n & 3, orow = g * 256 + h;
        g_Wp0[idx] = (k < 512) ? Wih0[orow * 512 + k] : Whh0[orow * 256 + (k - 512)];
    }
    for (int idx = bid * NTHR + tid; idx < 1024 * 512; idx += NBLK * NTHR) {
        int n = idx / 512, k = idx - n * 512;
        int h = n >> 2, g = n & 3, orow = g * 256 + h;
        g_Wp1[idx] = (k < 256) ? Wih1[orow * 256 + k] : Whh1[orow * 256 + (k - 256)];
    }
    for (int idx = bid * NTHR + tid; idx < 65536; idx += NBLK * NTHR) {
        int k = idx >> 8, h = idx & 255;
        g_WaT[idx] = Wa[h * 256 + k];
        g_Wstack[idx] = Wout[idx];
    }
    {
        int g = bid * NTHR + tid;           // 65536 threads exactly
        int i = g >> 8, j = g & 255;
        float acc = 0.f;
        const float* wc = Wcrit + i * 256;
#pragma unroll 4
        for (int k = 0; k < 256; k++) acc += wc[k] * Wout[k * 256 + j];
        g_Wstack[65536 + i * 256 + j] = acc;
    }
    for (int idx = bid * NTHR + tid; idx < 1024; idx += NBLK * NTHR) {
        int h = idx >> 2, g = idx & 3, orow = g * 256 + h;
        g_b0p[idx] = bih0[orow] + bhh0[orow];
        g_b1p[idx] = bih1[orow] + bhh1[orow];
    }
    for (int idx = bid * NTHR + tid; idx < Bq * 256; idx += NBLK * NTHR) {
        g_h0a[idx] = enc_h[idx]; g_h1a[idx] = enc_h[Bq * 256 + idx];
        g_c0[idx] = enc_c[idx];  g_c1[idx] = enc_c[Bq * 256 + idx];
        int b = idx >> 8, hh = idx & 255;
        const float* p = enc_out + (size_t)b * Lq * 256 + hh;
        float s = 0.f;
        for (int l = 0; l < Lq; l++) s += p[(size_t)l * 256];
        g_ctx[idx] = s * (1.0f / Lq);
    }
    bt += NBLK; gsync(bt);

    float *h0c = g_h0a, *h0n = g_h0b, *h1c = g_h1a, *h1n = g_h1b;
    const int bmL = (bid >> 4) * 128, bnL = (bid & 15) * 64;
    const int bmS = (bid >> 2) * 32,  bnS = (bid & 3) * 64;

    for (int t = 0; t < Lq; t++) {
        // P1: LSTM0 [emb(gather) | ctx | h0] K=768
        if (tid < 128)
            gidx[tid] = (t == 0) ? 0 : actions[(bmL + tid) * Lq + (t - 1)];
        __syncthreads();
        lstm_gemm(sp, gidx, bmL, bnL, emb, g_ctx, h0c, 768, true, g_Wp0, g_b0p, g_c0, h0n);
        bt += NBLK; gsync(bt);
        // P2: LSTM1 [h0n | h1c] K=512
        lstm_gemm(sp, gidx, bmL, bnL, h0n, h1c, nullptr, 512, false, g_Wp1, g_b1p, g_c1, h1n);
        bt += NBLK; gsync(bt);
        // P3: q = h1 @ Wa
        gemm_small(sp, bmS, bnS, h1n, nullptr, 256, g_WaT, nullptr, 0, g_q, bnS);
        bt += NBLK; gsync(bt);
        // P4: attention (single pass)
        attention8(sp, bid, enc_out);
        bt += NBLK; gsync(bt);
        // P5: ctx = tanh([h1|ctx_att] @ Wconcat^T)
        gemm_small(sp, bmS, bnS, h1n, g_ctx_att, 512, Wconcat, nullptr, 1, g_ctx, bnS);
        bt += NBLK; gsync(bt);
        // P6: [logit|Q] = ctx @ Wstack^T (2 tiles per block)
        {
            int T = bid;
            int bm = (T >> 3) * 32, bn = (T & 7) * 64;
            if (bn < 256) gemm_small(sp, bm, bn, g_ctx, nullptr, 256, g_Wstack, nullptr, 0, g_logit, bn);
            else          gemm_small(sp, bm, bn, g_ctx, nullptr, 256, g_Wstack, bcrit, 0, g_Q, bn - 256);
            T = bid + 128;
            bm = (T >> 3) * 32; bn = (T & 7) * 64;
            if (bn < 256) gemm_small(sp, bm, bn, g_ctx, nullptr, 256, g_Wstack, nullptr, 0, g_logit, bn);
            else          gemm_small(sp, bm, bn, g_ctx, nullptr, 256, g_Wstack, bcrit, 0, g_Q, bn - 256);
        }
        bt += NBLK; gsync(bt);
        // P7: finalize (no trailing barrier; next logit write is 5 gsyncs away)
        finalize8(bid, t, actions, out);
        float* tmp = h0c; h0c = h0n; h0n = tmp;
        tmp = h1c; h1c = h1n; h1n = tmp;
    }
}

__global__ void reset_k() { g_count = 0; }

// ---------------- host ----------------
extern "C" void kernel_launch(void* const* d_in, const int* in_sizes, int n_in,
                              void* d_out, int out_size) {
    const float* enc_out = (const float*)d_in[0];
    const float* enc_h   = (const float*)d_in[1];
    const float* enc_c   = (const float*)d_in[2];
    const float* emb     = (const float*)d_in[3];
    const float* Wih0    = (const float*)d_in[4];
    const float* Whh0    = (const float*)d_in[5];
    const float* bih0    = (const float*)d_in[6];
    const float* bhh0    = (const float*)d_in[7];
    const float* Wih1    = (const float*)d_in[8];
    const float* Whh1    = (const float*)d_in[9];
    const float* bih1    = (const float*)d_in[10];
    const float* bhh1    = (const float*)d_in[11];
    const float* Wa      = (const float*)d_in[12];
    const float* Wconcat = (const float*)d_in[13];
    const float* Wout    = (const float*)d_in[14];
    const float* Wcrit   = (const float*)d_in[15];
    const float* bcrit   = (const float*)d_in[16];
    const int*   actions = (const int*)d_in[17];
    float* out = (float*)d_out;

    const int smem = (int)sizeof(SPool);
    cudaFuncSetAttribute(mega, cudaFuncAttributeMaxDynamicSharedMemorySize, smem);
    reset_k<<<1, 1>>>();
    mega<<<NBLK, NTHR, smem>>>(enc_out, enc_h, enc_c, emb,
                               Wih0, Whh0, bih0, bhh0,
                               Wih1, Whh1, bih1, bhh1,
                               Wa, Wconcat, Wout, Wcrit, bcrit, actions, out);
}